// round 4
// baseline (speedup 1.0000x reference)
#include <cuda_runtime.h>

#define TOK   4096
#define DH    16384
#define DM    1024
#define KSEL  64
#define CMAX  192          // max near-boundary candidates per row
#define RWIN  4e-4f        // refinement window (abs), >> fp32 dot error

// ---- scratch (device globals; no runtime allocation) ----
__device__ float g_z[(long)TOK * DH];       // 256 MB post-ReLU pre-activations
__device__ int   g_idx[TOK * KSEL];
__device__ float g_val[TOK * KSEL];
__device__ int   g_cnt[TOK];

// ============================================================
// Encode: z = relu(x @ W_enc + b_enc), SIMT fp32 tiled GEMM
// M=4096, N=16384, K=1024. 128x128x16 tile, 256 thr, 8x8/thread
// Sequential ascending-k fp32 FMA accumulation per output.
// ============================================================
#define BM 128
#define BN 128
#define BK 16

__global__ __launch_bounds__(256) void encode_kernel(
    const float* __restrict__ A,     // x [TOK, DM]
    const float* __restrict__ B,     // W_enc [DM, DH]
    const float* __restrict__ bias)  // b_enc [DH]
{
    __shared__ float As[BK][BM];
    __shared__ float Bs[BK][BN];

    const int tid = threadIdx.x;
    const int tx = tid & 15;
    const int ty = tid >> 4;
    const int m0 = blockIdx.y * BM;
    const int n0 = blockIdx.x * BN;

    const int arow = tid >> 2;
    const int acol = (tid & 3) << 2;
    const int brow = tid >> 5;
    const int bcol = (tid & 31) << 2;

    const float* Ab = A + (long)m0 * DM;
    const float* Bb = B + n0;

    float acc[8][8];
#pragma unroll
    for (int i = 0; i < 8; i++)
#pragma unroll
        for (int j = 0; j < 8; j++) acc[i][j] = 0.f;

    float4 pa0 = *(const float4*)(Ab + (long)arow        * DM + acol);
    float4 pa1 = *(const float4*)(Ab + (long)(arow + 64) * DM + acol);
    float4 pb0 = *(const float4*)(Bb + (long)brow        * DH + bcol);
    float4 pb1 = *(const float4*)(Bb + (long)(brow + 8)  * DH + bcol);

    As[acol+0][arow]    = pa0.x; As[acol+1][arow]    = pa0.y;
    As[acol+2][arow]    = pa0.z; As[acol+3][arow]    = pa0.w;
    As[acol+0][arow+64] = pa1.x; As[acol+1][arow+64] = pa1.y;
    As[acol+2][arow+64] = pa1.z; As[acol+3][arow+64] = pa1.w;
    *(float4*)&Bs[brow][bcol]     = pb0;
    *(float4*)&Bs[brow + 8][bcol] = pb1;
    __syncthreads();

    for (int k0 = 0; k0 < DM; k0 += BK) {
        const bool more = (k0 + BK) < DM;
        if (more) {
            pa0 = *(const float4*)(Ab + (long)arow        * DM + (k0 + BK) + acol);
            pa1 = *(const float4*)(Ab + (long)(arow + 64) * DM + (k0 + BK) + acol);
            pb0 = *(const float4*)(Bb + (long)(k0 + BK + brow)     * DH + bcol);
            pb1 = *(const float4*)(Bb + (long)(k0 + BK + brow + 8) * DH + bcol);
        }
#pragma unroll
        for (int kk = 0; kk < BK; kk++) {
            float a[8], b[8];
            *(float4*)&a[0] = *(const float4*)&As[kk][ty * 4];
            *(float4*)&a[4] = *(const float4*)&As[kk][64 + ty * 4];
            *(float4*)&b[0] = *(const float4*)&Bs[kk][tx * 4];
            *(float4*)&b[4] = *(const float4*)&Bs[kk][64 + tx * 4];
#pragma unroll
            for (int i = 0; i < 8; i++)
#pragma unroll
                for (int j = 0; j < 8; j++)
                    acc[i][j] = fmaf(a[i], b[j], acc[i][j]);
        }
        __syncthreads();
        if (more) {
            As[acol+0][arow]    = pa0.x; As[acol+1][arow]    = pa0.y;
            As[acol+2][arow]    = pa0.z; As[acol+3][arow]    = pa0.w;
            As[acol+0][arow+64] = pa1.x; As[acol+1][arow+64] = pa1.y;
            As[acol+2][arow+64] = pa1.z; As[acol+3][arow+64] = pa1.w;
            *(float4*)&Bs[brow][bcol]     = pb0;
            *(float4*)&Bs[brow + 8][bcol] = pb1;
            __syncthreads();
        }
    }

    float bl[8];
#pragma unroll
    for (int j = 0; j < 8; j++) {
        int n = n0 + ((j < 4) ? (tx * 4 + j) : (64 + tx * 4 + (j - 4)));
        bl[j] = bias[n];
    }
#pragma unroll
    for (int i = 0; i < 8; i++) {
        int m = m0 + ((i < 4) ? (ty * 4 + i) : (64 + ty * 4 + (i - 4)));
        float* crow = g_z + (long)m * DH + n0;
        float4 o0, o1;
        o0.x = fmaxf(acc[i][0] + bl[0], 0.f);
        o0.y = fmaxf(acc[i][1] + bl[1], 0.f);
        o0.z = fmaxf(acc[i][2] + bl[2], 0.f);
        o0.w = fmaxf(acc[i][3] + bl[3], 0.f);
        o1.x = fmaxf(acc[i][4] + bl[4], 0.f);
        o1.y = fmaxf(acc[i][5] + bl[5], 0.f);
        o1.z = fmaxf(acc[i][6] + bl[6], 0.f);
        o1.w = fmaxf(acc[i][7] + bl[7], 0.f);
        *(float4*)(crow + tx * 4)      = o0;
        *(float4*)(crow + 64 + tx * 4) = o1;
    }
}

// ============================================================
// TopK with exact (fp64) boundary refinement.
// Binary-search threshold t on uint bit space (z >= 0).
// Elements > t+W are certainly-in; elements in [t-W, t+W] get
// exact fp64 recompute and are ranked exactly (index tiebreak).
// ============================================================
__global__ __launch_bounds__(256) void topk_kernel(
    const float* __restrict__ X,      // x [TOK, DM]
    const float* __restrict__ Wenc,   // [DM, DH]
    const float* __restrict__ benc)   // [DH]
{
    extern __shared__ unsigned sm[];   // DH values (64 KB)
    __shared__ int    s_red;
    __shared__ int    s_scan[256];
    __shared__ int    s_cidx[CMAX];
    __shared__ double s_cval[CMAX];
    __shared__ double s_wred[8];
    __shared__ int    s_cA, s_cC;

    const int row = blockIdx.x;
    const int tid = threadIdx.x;
    const unsigned* z = (const unsigned*)(g_z + (long)row * DH);

    // stage row in smem
    const uint4* z4 = (const uint4*)z;
    uint4* s4 = (uint4*)sm;
    for (int i = tid; i < DH / 4; i += 256) s4[i] = z4[i];
    __syncthreads();

    // largest t with count(v >= t) >= KSEL
    unsigned lo = 0u, hi = 0x7F800000u;
    while (lo < hi) {
        unsigned mid = lo + ((hi - lo + 1) >> 1);
        if (tid == 0) s_red = 0;
        __syncthreads();
        int c = 0;
#pragma unroll 8
        for (int i = 0; i < DH / 256; i++)
            c += (sm[i * 256 + tid] >= mid) ? 1 : 0;
#pragma unroll
        for (int o = 16; o; o >>= 1) c += __shfl_xor_sync(0xFFFFFFFFu, c, o);
        if ((tid & 31) == 0) atomicAdd(&s_red, c);
        __syncthreads();
        int cnt = s_red;
        if (cnt >= KSEL) lo = mid; else hi = mid - 1;
        __syncthreads();
    }
    const unsigned t = lo;
    const float tf = __uint_as_float(t);
    const int base = tid * (DH / 256);

    bool done = false;

    if (tf > 2.0f * RWIN) {
        const unsigned hib = __float_as_uint(tf + RWIN);
        const unsigned lob = __float_as_uint(tf - RWIN);

        // --- candidate count + gather (v in [lob, hib]) ---
        int nc = 0;
#pragma unroll 8
        for (int i = 0; i < DH / 256; i++) {
            unsigned v = sm[base + i];
            nc += (v >= lob && v <= hib) ? 1 : 0;
        }
        s_scan[tid] = nc;
        __syncthreads();
        for (int off = 1; off < 256; off <<= 1) {
            int v = (tid >= off) ? s_scan[tid - off] : 0;
            __syncthreads();
            s_scan[tid] += v;
            __syncthreads();
        }
        const int cC = s_scan[255];
        if (cC <= CMAX) {
            int cw = s_scan[tid] - nc;
            for (int i = 0; i < DH / 256; i++) {
                unsigned v = sm[base + i];
                if (v >= lob && v <= hib) s_cidx[cw++] = base + i;
            }
            __syncthreads();

            // --- pass A: certainly-in (v > hib), ascending index ---
            int ng = 0;
#pragma unroll 8
            for (int i = 0; i < DH / 256; i++) ng += (sm[base + i] > hib) ? 1 : 0;
            s_scan[tid] = ng;
            __syncthreads();
            for (int off = 1; off < 256; off <<= 1) {
                int v = (tid >= off) ? s_scan[tid - off] : 0;
                __syncthreads();
                s_scan[tid] += v;
                __syncthreads();
            }
            const int cA = s_scan[255];   // <= count(v>t) < KSEL
            int w = s_scan[tid] - ng;
            for (int i = 0; i < DH / 256; i++) {
                unsigned v = sm[base + i];
                if (v > hib) {
                    g_idx[row * KSEL + w] = base + i;
                    g_val[row * KSEL + w] = __uint_as_float(v);
                    w++;
                }
            }
            __syncthreads();

            // --- exact fp64 recompute of candidates (block-cooperative) ---
            const float* xr = X + (long)row * DM;
            for (int c = 0; c < cC; c++) {
                const int fi = s_cidx[c];
                double part = 0.0;
                for (int k = tid; k < DM; k += 256)
                    part += (double)xr[k] * (double)Wenc[(long)k * DH + fi];
#pragma unroll
                for (int o = 16; o; o >>= 1)
                    part += __shfl_down_sync(0xFFFFFFFFu, part, o);
                if ((tid & 31) == 0) s_wred[tid >> 5] = part;
                __syncthreads();
                if (tid == 0) {
                    double s = 0.0;
#pragma unroll
                    for (int wd = 0; wd < 8; wd++) s += s_wred[wd];
                    s += (double)benc[fi];
                    s_cval[c] = s > 0.0 ? s : 0.0;
                }
                __syncthreads();
            }

            // --- rank candidates by exact value desc, index asc; keep top need ---
            const int need = KSEL - cA;
            for (int c = tid; c < cC; c += 256) {
                const double v = s_cval[c];
                const int fi = s_cidx[c];
                int rank = 0;
                for (int c2 = 0; c2 < cC; c2++) {
                    const double u = s_cval[c2];
                    if (u > v || (u == v && s_cidx[c2] < fi)) rank++;
                }
                if (rank < need) {
                    g_idx[row * KSEL + cA + rank] = fi;
                    g_val[row * KSEL + cA + rank] = __uint_as_float(sm[fi]);
                }
            }
            if (tid == 0) g_cnt[row] = KSEL;
            done = true;
        }
        __syncthreads();
    }

    if (!done) {
        // ---- legacy fp32 path (t near zero, or candidate overflow) ----
        int ng = 0;
#pragma unroll 8
        for (int i = 0; i < DH / 256; i++) ng += (sm[base + i] > t) ? 1 : 0;
        s_scan[tid] = ng;
        __syncthreads();
        for (int off = 1; off < 256; off <<= 1) {
            int v = (tid >= off) ? s_scan[tid - off] : 0;
            __syncthreads();
            s_scan[tid] += v;
            __syncthreads();
        }
        const int c_gt = s_scan[255];
        int w = s_scan[tid] - ng;
        for (int i = 0; i < DH / 256; i++) {
            unsigned v = sm[base + i];
            if (v > t) {
                g_idx[row * KSEL + w] = base + i;
                g_val[row * KSEL + w] = __uint_as_float(v);
                w++;
            }
        }

        int cnt_final = c_gt;
        if (t != 0u) {
            __syncthreads();
            int ne = 0;
#pragma unroll 8
            for (int i = 0; i < DH / 256; i++) ne += (sm[base + i] == t) ? 1 : 0;
            s_scan[tid] = ne;
            __syncthreads();
            for (int off = 1; off < 256; off <<= 1) {
                int v = (tid >= off) ? s_scan[tid - off] : 0;
                __syncthreads();
                s_scan[tid] += v;
                __syncthreads();
            }
            int pos = c_gt + s_scan[tid] - ne;
            for (int i = 0; i < DH / 256; i++) {
                if (sm[base + i] == t) {
                    if (pos < KSEL) {
                        g_idx[row * KSEL + pos] = base + i;
                        g_val[row * KSEL + pos] = __uint_as_float(t);
                    }
                    pos++;
                }
            }
            cnt_final = KSEL;
        }
        if (tid == 0) g_cnt[row] = cnt_final;
    }
}

// ============================================================
// Decode: y[row,:] = b_dec + sum_j val_j * W_dec[idx_j, :]
// ============================================================
__global__ __launch_bounds__(256) void decode_kernel(
    const float* __restrict__ Wd,    // [DH, DM]
    const float* __restrict__ bd,    // [DM]
    float* __restrict__ Y)           // [TOK, DM]
{
    __shared__ float s_val[KSEL];
    __shared__ int   s_idx[KSEL];
    const int row = blockIdx.x;
    const int tid = threadIdx.x;
    const int cnt = g_cnt[row];

    if (tid < KSEL) {
        s_idx[tid] = (tid < cnt) ? g_idx[row * KSEL + tid] : 0;
        s_val[tid] = (tid < cnt) ? g_val[row * KSEL + tid] : 0.f;
    }
    __syncthreads();

    float4 acc = ((const float4*)bd)[tid];
#pragma unroll 4
    for (int j = 0; j < cnt; j++) {
        const float v = s_val[j];
        const float4 wv = ((const float4*)(Wd + (long)s_idx[j] * DM))[tid];
        acc.x = fmaf(v, wv.x, acc.x);
        acc.y = fmaf(v, wv.y, acc.y);
        acc.z = fmaf(v, wv.z, acc.z);
        acc.w = fmaf(v, wv.w, acc.w);
    }
    ((float4*)Y)[(long)row * (DM / 4) + tid] = acc;
}

// ============================================================
extern "C" void kernel_launch(void* const* d_in, const int* in_sizes, int n_in,
                              void* d_out, int out_size)
{
    const float* x     = (const float*)d_in[0];
    const float* W_enc = (const float*)d_in[1];
    const float* b_enc = (const float*)d_in[2];
    const float* W_dec = (const float*)d_in[3];
    const float* b_dec = (const float*)d_in[4];
    float* y = (float*)d_out;

    dim3 ge(DH / BN, TOK / BM);   // (128, 32)
    encode_kernel<<<ge, 256>>>(x, W_enc, b_enc);

    cudaFuncSetAttribute(topk_kernel,
                         cudaFuncAttributeMaxDynamicSharedMemorySize, DH * 4);
    topk_kernel<<<TOK, 256, DH * 4>>>(x, W_enc, b_enc);

    decode_kernel<<<TOK, 256>>>(W_dec, b_dec, y);
}